// round 5
// baseline (speedup 1.0000x reference)
#include <cuda_runtime.h>
#include <cstdint>

// ---------------- static device scratch (no allocations allowed) ----------------
__device__ float g_T3[4096 * 512];      // 8 MB : in-contracted activations (tf32 bits)
__device__ float g_U [4096 * 512];      // 8 MB : core-contracted activations (fp32)
__device__ float g_coreTF[512 * 512];   // 1 MB : core pre-converted to tf32 bits

__device__ __forceinline__ uint32_t f2tf32(float f) {
    uint32_t u;
    asm("cvt.rna.tf32.f32 %0, %1;" : "=r"(u) : "f"(f));
    return u;
}
__device__ __forceinline__ uint32_t smem_u32(const void* p) {
    uint32_t a;
    asm("{ .reg .u64 t; cvta.to.shared.u64 t, %1; cvt.u32.u64 %0, t; }" : "=r"(a) : "l"(p));
    return a;
}
#define CP_ASYNC16(dst, src) \
    asm volatile("cp.async.cg.shared.global [%0], [%1], 16;" :: "r"(dst), "l"(src) : "memory")
#define CP_COMMIT() asm volatile("cp.async.commit_group;" ::: "memory")
#define CP_WAIT(n)  asm volatile("cp.async.wait_group %0;" :: "n"(n) : "memory")

// ---------------- K0: pre-convert core to tf32 bits ----------------
__global__ __launch_bounds__(256) void k_cvtcore(const float* __restrict__ core) {
    int i = (blockIdx.x * 256 + threadIdx.x) * 4;
    float4 v = *(const float4*)(core + i);
    uint4 o = make_uint4(f2tf32(v.x), f2tf32(v.y), f2tf32(v.z), f2tf32(v.w));
    *(uint4*)(g_coreTF + i) = o;
}

// ---------------- K1: stage A, warp-per-sample ----------------
static constexpr int T1L = 272;
static constexpr int T2L = 144;
static constexpr int WSM = 8 * T1L + 8 * T2L;               // 3328 floats / warp
static constexpr int SMEM_A = (8 * WSM + 384) * 4;          // 108032 B

__global__ __launch_bounds__(256, 2) void k_stageA(const float* __restrict__ x,
                                                   const float* __restrict__ f3,
                                                   const float* __restrict__ f4,
                                                   const float* __restrict__ f5) {
    extern __shared__ float sm[];
    float* f3s = sm + 8 * WSM;
    float* f4s = f3s + 128;
    float* f5s = f4s + 128;

    int t = threadIdx.x, wid = t >> 5, lane = t & 31;
    if (t < 128) { f3s[t] = f3[t]; f4s[t] = f4[t]; f5s[t] = f5[t]; }
    __syncthreads();

    float* t1w = sm + wid * WSM;
    float* t2w = t1w + 8 * T1L;

    long s = (long)blockIdx.x * 8 + wid;
    const float* xs = x + s * 4096;

    // ---- phase 1 ----
    {
        float acc[8][8];
#pragma unroll
        for (int j = 0; j < 8; j++)
#pragma unroll
            for (int l = 0; l < 8; l++) acc[j][l] = 0.f;
#pragma unroll 4
        for (int d = 0; d < 16; d++) {
            float xv[8];
#pragma unroll
            for (int j = 0; j < 8; j++) xv[j] = xs[d * 256 + lane + 32 * j];
#pragma unroll
            for (int l = 0; l < 8; l++) {
                float fv = f3s[d * 8 + l];
#pragma unroll
                for (int j = 0; j < 8; j++) acc[j][l] += xv[j] * fv;
            }
        }
#pragma unroll
        for (int l = 0; l < 8; l++)
#pragma unroll
            for (int j = 0; j < 8; j++)
                t1w[l * T1L + lane + 32 * j] = acc[j][l];
    }
    __syncwarp();

    // ---- phase 2 ----
    {
        float acc[4][8];
#pragma unroll
        for (int q = 0; q < 4; q++)
#pragma unroll
            for (int m = 0; m < 8; m++) acc[q][m] = 0.f;
#pragma unroll
        for (int e = 0; e < 16; e++) {
            float tv[4];
#pragma unroll
            for (int q = 0; q < 4; q++) {
                int p = lane + 32 * q, l = p >> 4, f = p & 15;
                tv[q] = t1w[l * T1L + e * 16 + f];
            }
#pragma unroll
            for (int m = 0; m < 8; m++) {
                float fv = f4s[e * 8 + m];
#pragma unroll
                for (int q = 0; q < 4; q++) acc[q][m] += tv[q] * fv;
            }
        }
#pragma unroll
        for (int q = 0; q < 4; q++) {
            int p = lane + 32 * q, l = p >> 4, f = p & 15;
#pragma unroll
            for (int m = 0; m < 8; m++)
                t2w[l * T2L + m * 17 + f] = acc[q][m];
        }
    }
    __syncwarp();

    // ---- phase 3 -> g_T3 (tf32 bits) ----
    {
#pragma unroll
        for (int h = 0; h < 2; h++) {
            int lm = lane + 32 * h, l = lm >> 3, m = lm & 7;
            float acc[8];
#pragma unroll
            for (int n = 0; n < 8; n++) acc[n] = 0.f;
#pragma unroll
            for (int f = 0; f < 16; f++) {
                float tv = t2w[l * T2L + m * 17 + f];
#pragma unroll
                for (int n = 0; n < 8; n++) acc[n] += tv * f5s[f * 8 + n];
            }
            uint4* dst = (uint4*)(g_T3 + s * 512 + lm * 8);
            dst[0] = make_uint4(f2tf32(acc[0]), f2tf32(acc[1]), f2tf32(acc[2]), f2tf32(acc[3]));
            dst[1] = make_uint4(f2tf32(acc[4]), f2tf32(acc[5]), f2tf32(acc[6]), f2tf32(acc[7]));
        }
    }
}

// ---------------- K2: stage B via mma.sync tf32 + 3-deep cp.async pipeline ----------------
static constexpr int GS = 36;
static constexpr int GEMM_SMEM = 6 * 128 * GS * 4;   // 110592 B

__global__ __launch_bounds__(256) void k_gemm_mma() {
    extern __shared__ float sm[];
    uint32_t sm_u = smem_u32(sm);

    int t = threadIdx.x;
    int lane = t & 31, wid = t >> 5;
    int warp_m = (wid & 3) * 32;
    int warp_n = (wid >> 2) * 64;
    long s0 = (long)blockIdx.x * 128;
    int n0 = blockIdx.y * 128;

    int lrow = t >> 1;
    int lhalf = t & 1;
    const float* AG = g_T3 + (s0 + lrow) * 512 + lhalf * 16;
    const float* BG = g_coreTF + (size_t)(n0 + lrow) * 512 + lhalf * 16;
    uint32_t a_dst = (uint32_t)((lrow * GS + lhalf * 16) * 4);

    float acc[2][8][4];
#pragma unroll
    for (int mt = 0; mt < 2; mt++)
#pragma unroll
        for (int nt = 0; nt < 8; nt++)
#pragma unroll
            for (int i = 0; i < 4; i++) acc[mt][nt][i] = 0.f;

    int fr = lane >> 2, fc = lane & 3;

    // prologue: issue chunks 0,1
#pragma unroll
    for (int pc = 0; pc < 2; pc++) {
        uint32_t Au = sm_u + pc * 128 * GS * 4;
        uint32_t Bu = sm_u + (3 + pc) * 128 * GS * 4;
        const float* ag = AG + pc * 32;
        const float* bg = BG + pc * 32;
#pragma unroll
        for (int i = 0; i < 4; i++) {
            CP_ASYNC16(Au + a_dst + i * 16, ag + i * 4);
            CP_ASYNC16(Bu + a_dst + i * 16, bg + i * 4);
        }
        CP_COMMIT();
    }

#pragma unroll 1
    for (int c = 0; c < 16; c++) {
        int p = c % 3;
        if (c == 15) { CP_WAIT(0); } else { CP_WAIT(1); }
        __syncthreads();

        const float* As = sm + p * 128 * GS;
        const float* Bs = sm + (3 + p) * 128 * GS;
#pragma unroll
        for (int ks = 0; ks < 4; ks++) {
            int k0 = ks * 8;
            uint32_t a[2][4], b[8][2];
#pragma unroll
            for (int mt = 0; mt < 2; mt++) {
                const float* ab = As + (warp_m + mt * 16 + fr) * GS + k0 + fc;
                a[mt][0] = __float_as_uint(ab[0]);
                a[mt][1] = __float_as_uint(ab[8 * GS]);
                a[mt][2] = __float_as_uint(ab[4]);
                a[mt][3] = __float_as_uint(ab[8 * GS + 4]);
            }
#pragma unroll
            for (int nt = 0; nt < 8; nt++) {
                const float* bb = Bs + (warp_n + nt * 8 + fr) * GS + k0 + fc;
                b[nt][0] = __float_as_uint(bb[0]);
                b[nt][1] = __float_as_uint(bb[4]);
            }
#pragma unroll
            for (int mt = 0; mt < 2; mt++)
#pragma unroll
                for (int nt = 0; nt < 8; nt++)
                    asm volatile(
                        "mma.sync.aligned.m16n8k8.row.col.f32.tf32.tf32.f32 "
                        "{%0,%1,%2,%3}, {%4,%5,%6,%7}, {%8,%9}, {%0,%1,%2,%3};"
                        : "+f"(acc[mt][nt][0]), "+f"(acc[mt][nt][1]),
                          "+f"(acc[mt][nt][2]), "+f"(acc[mt][nt][3])
                        : "r"(a[mt][0]), "r"(a[mt][1]), "r"(a[mt][2]), "r"(a[mt][3]),
                          "r"(b[nt][0]), "r"(b[nt][1]));
        }

        if (c + 2 < 16) {
            int pn = (c + 2) % 3;
            uint32_t Au = sm_u + pn * 128 * GS * 4;
            uint32_t Bu = sm_u + (3 + pn) * 128 * GS * 4;
            const float* ag = AG + (c + 2) * 32;
            const float* bg = BG + (c + 2) * 32;
#pragma unroll
            for (int i = 0; i < 4; i++) {
                CP_ASYNC16(Au + a_dst + i * 16, ag + i * 4);
                CP_ASYNC16(Bu + a_dst + i * 16, bg + i * 4);
            }
            CP_COMMIT();
        }
    }

    // epilogue
    int cp = (lane & 3) * 2;
#pragma unroll
    for (int mt = 0; mt < 2; mt++)
#pragma unroll
        for (int h = 0; h < 2; h++) {
            long m = s0 + warp_m + mt * 16 + fr + h * 8;
            float* dst = g_U + m * 512 + n0 + warp_n + cp;
#pragma unroll
            for (int nt = 0; nt < 8; nt++) {
                float2 v = make_float2(acc[mt][nt][h * 2], acc[mt][nt][h * 2 + 1]);
                *(float2*)(dst + nt * 8) = v;
            }
        }
}

// ---------------- K3: stage C, warp-per-sample ----------------
// 8 samples/block (one per warp), no block barriers in main body.
//   u1[a, jk]  = sum_i f0[a,i] * U[i*64+jk]     (per-a stride 72)
//   u2[a, b, k]= sum_j f1[b,j] * u1[a, j*8+k]   (strides 148 / 9)
//   y[a,b,c]   = sum_k f2[c,k] * u2[a,b,k] + bias
static constexpr int U1S = 72;
static constexpr int U2S = 148;
static constexpr int CW = 16 * U1S + 16 * U2S;              // 3520 floats / warp
static constexpr int SMEM_C = (8 * CW + 384) * 4;           // 114176 B

__global__ __launch_bounds__(256, 2) void k_stageC(const float* __restrict__ f0,
                                                   const float* __restrict__ f1,
                                                   const float* __restrict__ f2,
                                                   const float* __restrict__ bias,
                                                   float* __restrict__ y) {
    extern __shared__ float sm[];
    float* f0s = sm + 8 * CW;
    float* f1s = f0s + 128;
    float* f2s = f1s + 128;

    int t = threadIdx.x, wid = t >> 5, lane = t & 31;
    if (t < 128) { f0s[t] = f0[t]; f1s[t] = f1[t]; f2s[t] = f2[t]; }
    __syncthreads();

    float* u1w = sm + wid * CW;          // 16 * 72
    float* u2w = u1w + 16 * U1S;         // 16 * 148

    long s = (long)blockIdx.x * 8 + wid;
    const float* Us = g_U + s * 512;

    // ---- phase 1: u1 ----
    {
        float acc[2][16];
#pragma unroll
        for (int h = 0; h < 2; h++)
#pragma unroll
            for (int a = 0; a < 16; a++) acc[h][a] = 0.f;
#pragma unroll
        for (int i = 0; i < 8; i++) {
            float uv0 = Us[i * 64 + lane];
            float uv1 = Us[i * 64 + lane + 32];
#pragma unroll
            for (int a = 0; a < 16; a++) {
                float fv = f0s[a * 8 + i];
                acc[0][a] += uv0 * fv;
                acc[1][a] += uv1 * fv;
            }
        }
#pragma unroll
        for (int a = 0; a < 16; a++) {
            u1w[a * U1S + lane]      = acc[0][a];
            u1w[a * U1S + lane + 32] = acc[1][a];
        }
    }
    __syncwarp();

    // ---- phase 2: u2 (4 (a,k) pairs per lane) ----
    {
        float acc[4][16];
#pragma unroll
        for (int h = 0; h < 4; h++)
#pragma unroll
            for (int b = 0; b < 16; b++) acc[h][b] = 0.f;
#pragma unroll
        for (int j = 0; j < 8; j++) {
            float tv[4];
#pragma unroll
            for (int h = 0; h < 4; h++) {
                int p = lane + 32 * h, a = p >> 3, k = p & 7;
                tv[h] = u1w[a * U1S + j * 8 + k];
            }
#pragma unroll
            for (int b = 0; b < 16; b++) {
                float fv = f1s[b * 8 + j];
#pragma unroll
                for (int h = 0; h < 4; h++) acc[h][b] += tv[h] * fv;
            }
        }
#pragma unroll
        for (int h = 0; h < 4; h++) {
            int p = lane + 32 * h, a = p >> 3, k = p & 7;
#pragma unroll
            for (int b = 0; b < 16; b++)
                u2w[a * U2S + b * 9 + k] = acc[h][b];
        }
    }
    __syncwarp();

    // ---- phase 3: y ----
    {
        float* ys = y + s * 4096;
#pragma unroll
        for (int r = 0; r < 8; r++) {
            int ab = lane + 32 * r, a = ab >> 4, b = ab & 15;
            float acc[16];
#pragma unroll
            for (int c = 0; c < 16; c++) acc[c] = 0.f;
#pragma unroll
            for (int k = 0; k < 8; k++) {
                float tv = u2w[a * U2S + b * 9 + k];
#pragma unroll
                for (int c = 0; c < 16; c++) acc[c] += tv * f2s[c * 8 + k];
            }
            const float4* bv = (const float4*)(bias + ab * 16);
            float4* dst = (float4*)(ys + ab * 16);
#pragma unroll
            for (int q = 0; q < 4; q++) {
                float4 bq = bv[q];
                dst[q] = make_float4(acc[q * 4 + 0] + bq.x, acc[q * 4 + 1] + bq.y,
                                     acc[q * 4 + 2] + bq.z, acc[q * 4 + 3] + bq.w);
            }
        }
    }
}

// ---------------- launch ----------------
extern "C" void kernel_launch(void* const* d_in, const int* in_sizes, int n_in,
                              void* d_out, int out_size) {
    const float* x    = (const float*)d_in[0];
    const float* core = (const float*)d_in[1];
    const float* f0   = (const float*)d_in[2];
    const float* f1   = (const float*)d_in[3];
    const float* f2   = (const float*)d_in[4];
    const float* f3   = (const float*)d_in[5];
    const float* f4   = (const float*)d_in[6];
    const float* f5   = (const float*)d_in[7];
    const float* bias = (const float*)d_in[8];
    float* y = (float*)d_out;

    int N = in_sizes[0] / 4096;

    cudaFuncSetAttribute(k_stageA, cudaFuncAttributeMaxDynamicSharedMemorySize, SMEM_A);
    cudaFuncSetAttribute(k_gemm_mma, cudaFuncAttributeMaxDynamicSharedMemorySize, GEMM_SMEM);
    cudaFuncSetAttribute(k_stageC, cudaFuncAttributeMaxDynamicSharedMemorySize, SMEM_C);

    k_cvtcore<<<256, 256>>>(core);
    k_stageA<<<N / 8, 256, SMEM_A>>>(x, f3, f4, f5);
    k_gemm_mma<<<dim3(N / 128, 4), 256, GEMM_SMEM>>>();
    k_stageC<<<N / 8, 256, SMEM_C>>>(f0, f1, f2, bias, y);
}

// round 7
// speedup vs baseline: 1.1485x; 1.1485x over previous
#include <cuda_runtime.h>
#include <cstdint>

// ---------------- static device scratch (no allocations allowed) ----------------
__device__ float g_T3[4096 * 512];      // 8 MB : in-contracted activations (tf32 bits)
__device__ float g_U [4096 * 512];      // 8 MB : core-contracted activations (fp32)
__device__ float g_coreTF[512 * 512];   // 1 MB : core pre-converted to tf32 bits

__device__ __forceinline__ uint32_t f2tf32(float f) {
    uint32_t u;
    asm("cvt.rna.tf32.f32 %0, %1;" : "=r"(u) : "f"(f));
    return u;
}
__device__ __forceinline__ uint32_t smem_u32(const void* p) {
    uint32_t a;
    asm("{ .reg .u64 t; cvta.to.shared.u64 t, %1; cvt.u32.u64 %0, t; }" : "=r"(a) : "l"(p));
    return a;
}
#define CP_ASYNC16(dst, src) \
    asm volatile("cp.async.cg.shared.global [%0], [%1], 16;" :: "r"(dst), "l"(src) : "memory")
#define CP_COMMIT() asm volatile("cp.async.commit_group;" ::: "memory")
#define CP_WAIT(n)  asm volatile("cp.async.wait_group %0;" :: "n"(n) : "memory")

// ---------------- K0: pre-convert core to tf32 bits ----------------
__global__ __launch_bounds__(256) void k_cvtcore(const float* __restrict__ core) {
    int i = (blockIdx.x * 256 + threadIdx.x) * 4;
    float4 v = *(const float4*)(core + i);
    uint4 o = make_uint4(f2tf32(v.x), f2tf32(v.y), f2tf32(v.z), f2tf32(v.w));
    *(uint4*)(g_coreTF + i) = o;
}

// ---------------- K1: stage A, warp-per-sample ----------------
static constexpr int T1L = 272;
static constexpr int T2L = 144;
static constexpr int WSM = 8 * T1L + 8 * T2L;               // 3328 floats / warp
static constexpr int SMEM_A = (8 * WSM + 384) * 4;          // 108032 B

__global__ __launch_bounds__(256, 2) void k_stageA(const float* __restrict__ x,
                                                   const float* __restrict__ f3,
                                                   const float* __restrict__ f4,
                                                   const float* __restrict__ f5) {
    extern __shared__ float sm[];
    float* f3s = sm + 8 * WSM;
    float* f4s = f3s + 128;
    float* f5s = f4s + 128;

    int t = threadIdx.x, wid = t >> 5, lane = t & 31;
    if (t < 128) { f3s[t] = f3[t]; f4s[t] = f4[t]; f5s[t] = f5[t]; }
    __syncthreads();

    float* t1w = sm + wid * WSM;
    float* t2w = t1w + 8 * T1L;

    long s = (long)blockIdx.x * 8 + wid;
    const float* xs = x + s * 4096;

    // ---- phase 1 ----
    {
        float acc[8][8];
#pragma unroll
        for (int j = 0; j < 8; j++)
#pragma unroll
            for (int l = 0; l < 8; l++) acc[j][l] = 0.f;
#pragma unroll 4
        for (int d = 0; d < 16; d++) {
            float xv[8];
#pragma unroll
            for (int j = 0; j < 8; j++) xv[j] = xs[d * 256 + lane + 32 * j];
#pragma unroll
            for (int l = 0; l < 8; l++) {
                float fv = f3s[d * 8 + l];
#pragma unroll
                for (int j = 0; j < 8; j++) acc[j][l] += xv[j] * fv;
            }
        }
#pragma unroll
        for (int l = 0; l < 8; l++)
#pragma unroll
            for (int j = 0; j < 8; j++)
                t1w[l * T1L + lane + 32 * j] = acc[j][l];
    }
    __syncwarp();

    // ---- phase 2 ----
    {
        float acc[4][8];
#pragma unroll
        for (int q = 0; q < 4; q++)
#pragma unroll
            for (int m = 0; m < 8; m++) acc[q][m] = 0.f;
#pragma unroll
        for (int e = 0; e < 16; e++) {
            float tv[4];
#pragma unroll
            for (int q = 0; q < 4; q++) {
                int p = lane + 32 * q, l = p >> 4, f = p & 15;
                tv[q] = t1w[l * T1L + e * 16 + f];
            }
#pragma unroll
            for (int m = 0; m < 8; m++) {
                float fv = f4s[e * 8 + m];
#pragma unroll
                for (int q = 0; q < 4; q++) acc[q][m] += tv[q] * fv;
            }
        }
#pragma unroll
        for (int q = 0; q < 4; q++) {
            int p = lane + 32 * q, l = p >> 4, f = p & 15;
#pragma unroll
            for (int m = 0; m < 8; m++)
                t2w[l * T2L + m * 17 + f] = acc[q][m];
        }
    }
    __syncwarp();

    // ---- phase 3 -> g_T3 (tf32 bits) ----
    {
#pragma unroll
        for (int h = 0; h < 2; h++) {
            int lm = lane + 32 * h, l = lm >> 3, m = lm & 7;
            float acc[8];
#pragma unroll
            for (int n = 0; n < 8; n++) acc[n] = 0.f;
#pragma unroll
            for (int f = 0; f < 16; f++) {
                float tv = t2w[l * T2L + m * 17 + f];
#pragma unroll
                for (int n = 0; n < 8; n++) acc[n] += tv * f5s[f * 8 + n];
            }
            uint4* dst = (uint4*)(g_T3 + s * 512 + lm * 8);
            dst[0] = make_uint4(f2tf32(acc[0]), f2tf32(acc[1]), f2tf32(acc[2]), f2tf32(acc[3]));
            dst[1] = make_uint4(f2tf32(acc[4]), f2tf32(acc[5]), f2tf32(acc[6]), f2tf32(acc[7]));
        }
    }
}

// ---------------- K2: stage B via mma.sync tf32 + 3-deep cp.async pipeline ----------------
static constexpr int GS = 36;
static constexpr int GEMM_SMEM = 6 * 128 * GS * 4;   // 110592 B

__global__ __launch_bounds__(256) void k_gemm_mma() {
    extern __shared__ float sm[];
    uint32_t sm_u = smem_u32(sm);

    int t = threadIdx.x;
    int lane = t & 31, wid = t >> 5;
    int warp_m = (wid & 3) * 32;
    int warp_n = (wid >> 2) * 64;
    long s0 = (long)blockIdx.x * 128;
    int n0 = blockIdx.y * 128;

    int lrow = t >> 1;
    int lhalf = t & 1;
    const float* AG = g_T3 + (s0 + lrow) * 512 + lhalf * 16;
    const float* BG = g_coreTF + (size_t)(n0 + lrow) * 512 + lhalf * 16;
    uint32_t a_dst = (uint32_t)((lrow * GS + lhalf * 16) * 4);

    float acc[2][8][4];
#pragma unroll
    for (int mt = 0; mt < 2; mt++)
#pragma unroll
        for (int nt = 0; nt < 8; nt++)
#pragma unroll
            for (int i = 0; i < 4; i++) acc[mt][nt][i] = 0.f;

    int fr = lane >> 2, fc = lane & 3;

    // prologue: issue chunks 0,1
#pragma unroll
    for (int pc = 0; pc < 2; pc++) {
        uint32_t Au = sm_u + pc * 128 * GS * 4;
        uint32_t Bu = sm_u + (3 + pc) * 128 * GS * 4;
        const float* ag = AG + pc * 32;
        const float* bg = BG + pc * 32;
#pragma unroll
        for (int i = 0; i < 4; i++) {
            CP_ASYNC16(Au + a_dst + i * 16, ag + i * 4);
            CP_ASYNC16(Bu + a_dst + i * 16, bg + i * 4);
        }
        CP_COMMIT();
    }

#pragma unroll 1
    for (int c = 0; c < 16; c++) {
        int p = c % 3;
        if (c == 15) { CP_WAIT(0); } else { CP_WAIT(1); }
        __syncthreads();

        const float* As = sm + p * 128 * GS;
        const float* Bs = sm + (3 + p) * 128 * GS;
#pragma unroll
        for (int ks = 0; ks < 4; ks++) {
            int k0 = ks * 8;
            uint32_t a[2][4], b[8][2];
#pragma unroll
            for (int mt = 0; mt < 2; mt++) {
                const float* ab = As + (warp_m + mt * 16 + fr) * GS + k0 + fc;
                a[mt][0] = __float_as_uint(ab[0]);
                a[mt][1] = __float_as_uint(ab[8 * GS]);
                a[mt][2] = __float_as_uint(ab[4]);
                a[mt][3] = __float_as_uint(ab[8 * GS + 4]);
            }
#pragma unroll
            for (int nt = 0; nt < 8; nt++) {
                const float* bb = Bs + (warp_n + nt * 8 + fr) * GS + k0 + fc;
                b[nt][0] = __float_as_uint(bb[0]);
                b[nt][1] = __float_as_uint(bb[4]);
            }
#pragma unroll
            for (int mt = 0; mt < 2; mt++)
#pragma unroll
                for (int nt = 0; nt < 8; nt++)
                    asm volatile(
                        "mma.sync.aligned.m16n8k8.row.col.f32.tf32.tf32.f32 "
                        "{%0,%1,%2,%3}, {%4,%5,%6,%7}, {%8,%9}, {%0,%1,%2,%3};"
                        : "+f"(acc[mt][nt][0]), "+f"(acc[mt][nt][1]),
                          "+f"(acc[mt][nt][2]), "+f"(acc[mt][nt][3])
                        : "r"(a[mt][0]), "r"(a[mt][1]), "r"(a[mt][2]), "r"(a[mt][3]),
                          "r"(b[nt][0]), "r"(b[nt][1]));
        }

        if (c + 2 < 16) {
            int pn = (c + 2) % 3;
            uint32_t Au = sm_u + pn * 128 * GS * 4;
            uint32_t Bu = sm_u + (3 + pn) * 128 * GS * 4;
            const float* ag = AG + (c + 2) * 32;
            const float* bg = BG + (c + 2) * 32;
#pragma unroll
            for (int i = 0; i < 4; i++) {
                CP_ASYNC16(Au + a_dst + i * 16, ag + i * 4);
                CP_ASYNC16(Bu + a_dst + i * 16, bg + i * 4);
            }
            CP_COMMIT();
        }
    }

    // epilogue
    int cp = (lane & 3) * 2;
#pragma unroll
    for (int mt = 0; mt < 2; mt++)
#pragma unroll
        for (int h = 0; h < 2; h++) {
            long m = s0 + warp_m + mt * 16 + fr + h * 8;
            float* dst = g_U + m * 512 + n0 + warp_n + cp;
#pragma unroll
            for (int nt = 0; nt < 8; nt++) {
                float2 v = make_float2(acc[mt][nt][h * 2], acc[mt][nt][h * 2 + 1]);
                *(float2*)(dst + nt * 8) = v;
            }
        }
}

// ---------------- K3: stage C, warp-per-sample, register-capped ----------------
//   u1[a, jk]  = sum_i f0[a,i] * U[i*64+jk]     (per-a stride 72)
//   u2[a, b, k]= sum_j f1[b,j] * u1[a, j*8+k]   (strides 144 / 9; extent 143 <= 144)
//   y[a,b,c]   = sum_k f2[c,k] * u2[a,b,k] + bias
static constexpr int U1S = 72;
static constexpr int U2S = 144;
static constexpr int CW = 16 * U1S + 16 * U2S;              // 3456 floats / warp
static constexpr int SMEM_C = (8 * CW + 384) * 4;           // 112128 B

__global__ __launch_bounds__(256, 2) void k_stageC(const float* __restrict__ f0,
                                                   const float* __restrict__ f1,
                                                   const float* __restrict__ f2,
                                                   const float* __restrict__ bias,
                                                   float* __restrict__ y) {
    extern __shared__ float sm[];
    float* f0s = sm + 8 * CW;
    float* f1s = f0s + 128;
    float* f2s = f1s + 128;

    int t = threadIdx.x, wid = t >> 5, lane = t & 31;
    if (t < 128) { f0s[t] = f0[t]; f1s[t] = f1[t]; f2s[t] = f2[t]; }
    __syncthreads();

    float* u1w = sm + wid * CW;          // 16 * 72
    float* u2w = u1w + 16 * U1S;         // 16 * 144

    long s = (long)blockIdx.x * 8 + wid;
    const float* Us = g_U + s * 512;

    // ---- phase 1: u1 (acc 32 regs) ----
    {
        float acc[2][16];
#pragma unroll
        for (int h = 0; h < 2; h++)
#pragma unroll
            for (int a = 0; a < 16; a++) acc[h][a] = 0.f;
#pragma unroll
        for (int i = 0; i < 8; i++) {
            float uv0 = Us[i * 64 + lane];
            float uv1 = Us[i * 64 + lane + 32];
#pragma unroll
            for (int a = 0; a < 16; a++) {
                float fv = f0s[a * 8 + i];
                acc[0][a] += uv0 * fv;
                acc[1][a] += uv1 * fv;
            }
        }
#pragma unroll
        for (int a = 0; a < 16; a++) {
            u1w[a * U1S + lane]      = acc[0][a];
            u1w[a * U1S + lane + 32] = acc[1][a];
        }
    }
    __syncwarp();

    // ---- phase 2: u2, b split in two groups of 8 (acc 32 regs) ----
#pragma unroll 1
    for (int g = 0; g < 2; g++) {
        float acc[4][8];
#pragma unroll
        for (int h = 0; h < 4; h++)
#pragma unroll
            for (int b8 = 0; b8 < 8; b8++) acc[h][b8] = 0.f;
#pragma unroll
        for (int j = 0; j < 8; j++) {
            float tv[4];
#pragma unroll
            for (int h = 0; h < 4; h++) {
                int p = lane + 32 * h, a = p >> 3, k = p & 7;
                tv[h] = u1w[a * U1S + j * 8 + k];
            }
#pragma unroll
            for (int b8 = 0; b8 < 8; b8++) {
                float fv = f1s[(g * 8 + b8) * 8 + j];
#pragma unroll
                for (int h = 0; h < 4; h++) acc[h][b8] += tv[h] * fv;
            }
        }
#pragma unroll
        for (int h = 0; h < 4; h++) {
            int p = lane + 32 * h, a = p >> 3, k = p & 7;
#pragma unroll
            for (int b8 = 0; b8 < 8; b8++)
                u2w[a * U2S + (g * 8 + b8) * 9 + k] = acc[h][b8];
        }
    }
    __syncwarp();

    // ---- phase 3: y (unroll 2 to cap regs) ----
    {
        float* ys = y + s * 4096;
#pragma unroll 2
        for (int r = 0; r < 8; r++) {
            int ab = lane + 32 * r, a = ab >> 4, b = ab & 15;
            float acc[16];
#pragma unroll
            for (int c = 0; c < 16; c++) acc[c] = 0.f;
#pragma unroll
            for (int k = 0; k < 8; k++) {
                float tv = u2w[a * U2S + b * 9 + k];
#pragma unroll
                for (int c = 0; c < 16; c++) acc[c] += tv * f2s[c * 8 + k];
            }
            const float4* bv = (const float4*)(bias + ab * 16);
            float4* dst = (float4*)(ys + ab * 16);
#pragma unroll
            for (int q = 0; q < 4; q++) {
                float4 bq = bv[q];
                dst[q] = make_float4(acc[q * 4 + 0] + bq.x, acc[q * 4 + 1] + bq.y,
                                     acc[q * 4 + 2] + bq.z, acc[q * 4 + 3] + bq.w);
            }
        }
    }
}

// ---------------- launch ----------------
extern "C" void kernel_launch(void* const* d_in, const int* in_sizes, int n_in,
                              void* d_out, int out_size) {
    const float* x    = (const float*)d_in[0];
    const float* core = (const float*)d_in[1];
    const float* f0   = (const float*)d_in[2];
    const float* f1   = (const float*)d_in[3];
    const float* f2   = (const float*)d_in[4];
    const float* f3   = (const float*)d_in[5];
    const float* f4   = (const float*)d_in[6];
    const float* f5   = (const float*)d_in[7];
    const float* bias = (const float*)d_in[8];
    float* y = (float*)d_out;

    int N = in_sizes[0] / 4096;

    cudaFuncSetAttribute(k_stageA, cudaFuncAttributeMaxDynamicSharedMemorySize, SMEM_A);
    cudaFuncSetAttribute(k_gemm_mma, cudaFuncAttributeMaxDynamicSharedMemorySize, GEMM_SMEM);
    cudaFuncSetAttribute(k_stageC, cudaFuncAttributeMaxDynamicSharedMemorySize, SMEM_C);

    k_cvtcore<<<256, 256>>>(core);
    k_stageA<<<N / 8, 256, SMEM_A>>>(x, f3, f4, f5);
    k_gemm_mma<<<dim3(N / 128, 4), 256, GEMM_SMEM>>>();
    k_stageC<<<N / 8, 256, SMEM_C>>>(f0, f1, f2, bias, y);
}

// round 8
// speedup vs baseline: 1.5847x; 1.3797x over previous
#include <cuda_runtime.h>
#include <cstdint>

// ---------------- static device scratch (no allocations allowed) ----------------
__device__ float g_T3[4096 * 512];      // 8 MB : in-contracted activations (tf32 bits)
__device__ float g_U [4096 * 512];      // 8 MB : core-contracted activations (fp32)
__device__ float g_coreTF[512 * 512];   // 1 MB : core pre-converted to tf32 bits

__device__ __forceinline__ uint32_t f2tf32(float f) {
    uint32_t u;
    asm("cvt.rna.tf32.f32 %0, %1;" : "=r"(u) : "f"(f));
    return u;
}
__device__ __forceinline__ uint32_t smem_u32(const void* p) {
    uint32_t a;
    asm("{ .reg .u64 t; cvta.to.shared.u64 t, %1; cvt.u32.u64 %0, t; }" : "=r"(a) : "l"(p));
    return a;
}
#define CP_ASYNC16(dst, src) \
    asm volatile("cp.async.cg.shared.global [%0], [%1], 16;" :: "r"(dst), "l"(src) : "memory")
#define CP_COMMIT() asm volatile("cp.async.commit_group;" ::: "memory")
#define CP_WAIT(n)  asm volatile("cp.async.wait_group %0;" :: "n"(n) : "memory")

// ---------------- K0: pre-convert core to tf32 bits ----------------
__global__ __launch_bounds__(256) void k_cvtcore(const float* __restrict__ core) {
    int i = (blockIdx.x * 256 + threadIdx.x) * 4;
    float4 v = *(const float4*)(core + i);
    uint4 o = make_uint4(f2tf32(v.x), f2tf32(v.y), f2tf32(v.z), f2tf32(v.w));
    *(uint4*)(g_coreTF + i) = o;
}

// ---------------- K1: stage A, warp-per-sample ----------------
static constexpr int T1L = 272;
static constexpr int T2L = 144;
static constexpr int WSM = 8 * T1L + 8 * T2L;               // 3328 floats / warp
static constexpr int SMEM_A = (8 * WSM + 384) * 4;          // 108032 B

__global__ __launch_bounds__(256, 2) void k_stageA(const float* __restrict__ x,
                                                   const float* __restrict__ f3,
                                                   const float* __restrict__ f4,
                                                   const float* __restrict__ f5) {
    extern __shared__ float sm[];
    float* f3s = sm + 8 * WSM;
    float* f4s = f3s + 128;
    float* f5s = f4s + 128;

    int t = threadIdx.x, wid = t >> 5, lane = t & 31;
    if (t < 128) { f3s[t] = f3[t]; f4s[t] = f4[t]; f5s[t] = f5[t]; }
    __syncthreads();

    float* t1w = sm + wid * WSM;
    float* t2w = t1w + 8 * T1L;

    long s = (long)blockIdx.x * 8 + wid;
    const float* xs = x + s * 4096;

    // ---- phase 1 ----
    {
        float acc[8][8];
#pragma unroll
        for (int j = 0; j < 8; j++)
#pragma unroll
            for (int l = 0; l < 8; l++) acc[j][l] = 0.f;
#pragma unroll 4
        for (int d = 0; d < 16; d++) {
            float xv[8];
#pragma unroll
            for (int j = 0; j < 8; j++) xv[j] = xs[d * 256 + lane + 32 * j];
#pragma unroll
            for (int l = 0; l < 8; l++) {
                float fv = f3s[d * 8 + l];
#pragma unroll
                for (int j = 0; j < 8; j++) acc[j][l] += xv[j] * fv;
            }
        }
#pragma unroll
        for (int l = 0; l < 8; l++)
#pragma unroll
            for (int j = 0; j < 8; j++)
                t1w[l * T1L + lane + 32 * j] = acc[j][l];
    }
    __syncwarp();

    // ---- phase 2 ----
    {
        float acc[4][8];
#pragma unroll
        for (int q = 0; q < 4; q++)
#pragma unroll
            for (int m = 0; m < 8; m++) acc[q][m] = 0.f;
#pragma unroll
        for (int e = 0; e < 16; e++) {
            float tv[4];
#pragma unroll
            for (int q = 0; q < 4; q++) {
                int p = lane + 32 * q, l = p >> 4, f = p & 15;
                tv[q] = t1w[l * T1L + e * 16 + f];
            }
#pragma unroll
            for (int m = 0; m < 8; m++) {
                float fv = f4s[e * 8 + m];
#pragma unroll
                for (int q = 0; q < 4; q++) acc[q][m] += tv[q] * fv;
            }
        }
#pragma unroll
        for (int q = 0; q < 4; q++) {
            int p = lane + 32 * q, l = p >> 4, f = p & 15;
#pragma unroll
            for (int m = 0; m < 8; m++)
                t2w[l * T2L + m * 17 + f] = acc[q][m];
        }
    }
    __syncwarp();

    // ---- phase 3 -> g_T3 (tf32 bits) ----
    {
#pragma unroll
        for (int h = 0; h < 2; h++) {
            int lm = lane + 32 * h, l = lm >> 3, m = lm & 7;
            float acc[8];
#pragma unroll
            for (int n = 0; n < 8; n++) acc[n] = 0.f;
#pragma unroll
            for (int f = 0; f < 16; f++) {
                float tv = t2w[l * T2L + m * 17 + f];
#pragma unroll
                for (int n = 0; n < 8; n++) acc[n] += tv * f5s[f * 8 + n];
            }
            uint4* dst = (uint4*)(g_T3 + s * 512 + lm * 8);
            dst[0] = make_uint4(f2tf32(acc[0]), f2tf32(acc[1]), f2tf32(acc[2]), f2tf32(acc[3]));
            dst[1] = make_uint4(f2tf32(acc[4]), f2tf32(acc[5]), f2tf32(acc[6]), f2tf32(acc[7]));
        }
    }
}

// ---------------- K2: stage B via mma.sync tf32, 512 threads, 3-deep pipeline ----------------
// 128x128 tile, 16 warps (4m x 4n), each warp 32x32. K chunks of 32.
static constexpr int GS = 36;
static constexpr int GEMM_SMEM = 6 * 128 * GS * 4;   // 110592 B

__global__ __launch_bounds__(512) void k_gemm_mma() {
    extern __shared__ float sm[];
    uint32_t sm_u = smem_u32(sm);

    int t = threadIdx.x;
    int lane = t & 31, wid = t >> 5;
    int warp_m = (wid & 3) * 32;
    int warp_n = (wid >> 2) * 32;
    long s0 = (long)blockIdx.x * 128;
    int n0 = blockIdx.y * 128;

    // load mapping: two float4 per thread per operand per chunk
    int i0 = t, i1 = t + 512;
    int r0 = i0 >> 3, c0v = (i0 & 7) * 4;
    int r1 = i1 >> 3, c1v = (i1 & 7) * 4;
    const float* AG0 = g_T3 + (s0 + r0) * 512 + c0v;
    const float* AG1 = g_T3 + (s0 + r1) * 512 + c1v;
    const float* BG0 = g_coreTF + (size_t)(n0 + r0) * 512 + c0v;
    const float* BG1 = g_coreTF + (size_t)(n0 + r1) * 512 + c1v;
    uint32_t d0 = (uint32_t)((r0 * GS + c0v) * 4);
    uint32_t d1 = (uint32_t)((r1 * GS + c1v) * 4);

    float acc[2][4][4];
#pragma unroll
    for (int mt = 0; mt < 2; mt++)
#pragma unroll
        for (int nt = 0; nt < 4; nt++)
#pragma unroll
            for (int i = 0; i < 4; i++) acc[mt][nt][i] = 0.f;

    int fr = lane >> 2, fc = lane & 3;

    // prologue: issue chunks 0,1
#pragma unroll
    for (int pc = 0; pc < 2; pc++) {
        uint32_t Au = sm_u + pc * 128 * GS * 4;
        uint32_t Bu = sm_u + (3 + pc) * 128 * GS * 4;
        CP_ASYNC16(Au + d0, AG0 + pc * 32);
        CP_ASYNC16(Au + d1, AG1 + pc * 32);
        CP_ASYNC16(Bu + d0, BG0 + pc * 32);
        CP_ASYNC16(Bu + d1, BG1 + pc * 32);
        CP_COMMIT();
    }

#pragma unroll 1
    for (int c = 0; c < 16; c++) {
        int p = c % 3;
        if (c == 15) { CP_WAIT(0); } else { CP_WAIT(1); }
        __syncthreads();

        const float* As = sm + p * 128 * GS;
        const float* Bs = sm + (3 + p) * 128 * GS;
#pragma unroll
        for (int ks = 0; ks < 4; ks++) {
            int k0 = ks * 8;
            uint32_t a[2][4], b[4][2];
#pragma unroll
            for (int mt = 0; mt < 2; mt++) {
                const float* ab = As + (warp_m + mt * 16 + fr) * GS + k0 + fc;
                a[mt][0] = __float_as_uint(ab[0]);
                a[mt][1] = __float_as_uint(ab[8 * GS]);
                a[mt][2] = __float_as_uint(ab[4]);
                a[mt][3] = __float_as_uint(ab[8 * GS + 4]);
            }
#pragma unroll
            for (int nt = 0; nt < 4; nt++) {
                const float* bb = Bs + (warp_n + nt * 8 + fr) * GS + k0 + fc;
                b[nt][0] = __float_as_uint(bb[0]);
                b[nt][1] = __float_as_uint(bb[4]);
            }
#pragma unroll
            for (int mt = 0; mt < 2; mt++)
#pragma unroll
                for (int nt = 0; nt < 4; nt++)
                    asm volatile(
                        "mma.sync.aligned.m16n8k8.row.col.f32.tf32.tf32.f32 "
                        "{%0,%1,%2,%3}, {%4,%5,%6,%7}, {%8,%9}, {%0,%1,%2,%3};"
                        : "+f"(acc[mt][nt][0]), "+f"(acc[mt][nt][1]),
                          "+f"(acc[mt][nt][2]), "+f"(acc[mt][nt][3])
                        : "r"(a[mt][0]), "r"(a[mt][1]), "r"(a[mt][2]), "r"(a[mt][3]),
                          "r"(b[nt][0]), "r"(b[nt][1]));
        }

        if (c + 2 < 16) {
            int pn = (c + 2) % 3;
            uint32_t Au = sm_u + pn * 128 * GS * 4;
            uint32_t Bu = sm_u + (3 + pn) * 128 * GS * 4;
            int off = (c + 2) * 32;
            CP_ASYNC16(Au + d0, AG0 + off);
            CP_ASYNC16(Au + d1, AG1 + off);
            CP_ASYNC16(Bu + d0, BG0 + off);
            CP_ASYNC16(Bu + d1, BG1 + off);
            CP_COMMIT();
        }
    }

    // epilogue
    int cp = (lane & 3) * 2;
#pragma unroll
    for (int mt = 0; mt < 2; mt++)
#pragma unroll
        for (int h = 0; h < 2; h++) {
            long m = s0 + warp_m + mt * 16 + fr + h * 8;
            float* dst = g_U + m * 512 + n0 + warp_n + cp;
#pragma unroll
            for (int nt = 0; nt < 4; nt++) {
                float2 v = make_float2(acc[mt][nt][h * 2], acc[mt][nt][h * 2 + 1]);
                *(float2*)(dst + nt * 8) = v;
            }
        }
}

// ---------------- K3: stage C (block version, 4 samples/block — reverted R4) ----------------
__global__ __launch_bounds__(256) void k_stageC(const float* __restrict__ f0,
                                                const float* __restrict__ f1,
                                                const float* __restrict__ f2,
                                                const float* __restrict__ bias,
                                                float* __restrict__ y) {
    extern __shared__ float sm[];
    float* u1s = sm;                    // 4 * 1152
    float* u2s = sm + 4 * 1152;         // 4 * 2176
    float* f0s = u2s + 4 * 2176;
    float* f1s = f0s + 128;
    float* f2s = f1s + 128;

    int t = threadIdx.x;
    if (t < 128) { f0s[t] = f0[t]; f1s[t] = f1[t]; f2s[t] = f2[t]; }
    __syncthreads();

    long s0 = (long)blockIdx.x * 4;

    {
        int g = t >> 6, jk = t & 63;
        float acc[4][4];
#pragma unroll
        for (int s = 0; s < 4; s++)
#pragma unroll
            for (int a4 = 0; a4 < 4; a4++) acc[s][a4] = 0.f;
#pragma unroll
        for (int i = 0; i < 8; i++) {
            float uv0 = g_U[(s0 + 0) * 512 + i * 64 + jk];
            float uv1 = g_U[(s0 + 1) * 512 + i * 64 + jk];
            float uv2 = g_U[(s0 + 2) * 512 + i * 64 + jk];
            float uv3 = g_U[(s0 + 3) * 512 + i * 64 + jk];
#pragma unroll
            for (int a4 = 0; a4 < 4; a4++) {
                float fv = f0s[(g * 4 + a4) * 8 + i];
                acc[0][a4] += uv0 * fv; acc[1][a4] += uv1 * fv;
                acc[2][a4] += uv2 * fv; acc[3][a4] += uv3 * fv;
            }
        }
#pragma unroll
        for (int s = 0; s < 4; s++)
#pragma unroll
            for (int a4 = 0; a4 < 4; a4++)
                u1s[s * 1152 + (g * 4 + a4) * 72 + jk] = acc[s][a4];
    }
    __syncthreads();

    {
        int h = t >> 7, pair = t & 127;
        int a = pair >> 3, k = pair & 7;
        float acc[2][16];
#pragma unroll
        for (int z = 0; z < 2; z++)
#pragma unroll
            for (int b = 0; b < 16; b++) acc[z][b] = 0.f;
#pragma unroll
        for (int j = 0; j < 8; j++) {
            float tv0 = u1s[(2 * h + 0) * 1152 + a * 72 + j * 8 + k];
            float tv1 = u1s[(2 * h + 1) * 1152 + a * 72 + j * 8 + k];
#pragma unroll
            for (int b = 0; b < 16; b++) {
                float fv = f1s[b * 8 + j];
                acc[0][b] += tv0 * fv; acc[1][b] += tv1 * fv;
            }
        }
#pragma unroll
        for (int z = 0; z < 2; z++)
#pragma unroll
            for (int b = 0; b < 16; b++)
                u2s[(2 * h + z) * 2176 + a * 136 + b * 8 + k] = acc[z][b];
    }
    __syncthreads();

    {
        int q = t & 3, ab0 = t >> 2;
#pragma unroll
        for (int r = 0; r < 4; r++) {
            int ab = ab0 + 64 * r;
            int a = ab >> 4, b = ab & 15;
            float acc[4][4];
#pragma unroll
            for (int s = 0; s < 4; s++)
#pragma unroll
                for (int c4 = 0; c4 < 4; c4++) acc[s][c4] = 0.f;
#pragma unroll
            for (int k = 0; k < 8; k++) {
                float tv0 = u2s[0 * 2176 + a * 136 + b * 8 + k];
                float tv1 = u2s[1 * 2176 + a * 136 + b * 8 + k];
                float tv2 = u2s[2 * 2176 + a * 136 + b * 8 + k];
                float tv3 = u2s[3 * 2176 + a * 136 + b * 8 + k];
#pragma unroll
                for (int c4 = 0; c4 < 4; c4++) {
                    float fv = f2s[(q * 4 + c4) * 8 + k];
                    acc[0][c4] += tv0 * fv; acc[1][c4] += tv1 * fv;
                    acc[2][c4] += tv2 * fv; acc[3][c4] += tv3 * fv;
                }
            }
            float4 bv = *(const float4*)&bias[ab * 16 + q * 4];
#pragma unroll
            for (int s = 0; s < 4; s++) {
                float4 o = make_float4(acc[s][0] + bv.x, acc[s][1] + bv.y,
                                       acc[s][2] + bv.z, acc[s][3] + bv.w);
                *(float4*)&y[(s0 + s) * 4096 + ab * 16 + q * 4] = o;
            }
        }
    }
}

// ---------------- launch ----------------
extern "C" void kernel_launch(void* const* d_in, const int* in_sizes, int n_in,
                              void* d_out, int out_size) {
    const float* x    = (const float*)d_in[0];
    const float* core = (const float*)d_in[1];
    const float* f0   = (const float*)d_in[2];
    const float* f1   = (const float*)d_in[3];
    const float* f2   = (const float*)d_in[4];
    const float* f3   = (const float*)d_in[5];
    const float* f4   = (const float*)d_in[6];
    const float* f5   = (const float*)d_in[7];
    const float* bias = (const float*)d_in[8];
    float* y = (float*)d_out;

    int N = in_sizes[0] / 4096;

    const int SMEM_C = (4 * 1152 + 4 * 2176 + 384) * 4;   // 54784

    cudaFuncSetAttribute(k_stageA, cudaFuncAttributeMaxDynamicSharedMemorySize, SMEM_A);
    cudaFuncSetAttribute(k_gemm_mma, cudaFuncAttributeMaxDynamicSharedMemorySize, GEMM_SMEM);
    cudaFuncSetAttribute(k_stageC, cudaFuncAttributeMaxDynamicSharedMemorySize, SMEM_C);

    k_cvtcore<<<256, 256>>>(core);
    k_stageA<<<N / 8, 256, SMEM_A>>>(x, f3, f4, f5);
    k_gemm_mma<<<dim3(N / 128, 4), 512, GEMM_SMEM>>>();
    k_stageC<<<N / 4, 256, SMEM_C>>>(f0, f1, f2, bias, y);
}